// round 7
// baseline (speedup 1.0000x reference)
#include <cuda_runtime.h>
#include <cstdint>

#define CH_IN 32
#define CH_Y  16
#define IMG_H 256
#define IMG_W 256
#define NB    16
#define CHS   (IMG_H * IMG_W)   // channel stride (elements)
#define CHS4  (CHS / 4)
#define CHS2  (CHS / 2)
#define NT    128               // threads/block; one (b,h) row, 2 px/thread

union F2U { float2 f; uint64_t u; };
union F4U { float4 f; ulonglong2 u2; };

// sm_103a packed dual-fp32 ops (ptxas never emits these from C++)
__device__ __forceinline__ void fma2(uint64_t& d, uint64_t a, uint64_t b) {
    asm("fma.rn.f32x2 %0, %1, %2, %0;" : "+l"(d) : "l"(a), "l"(b));
}
__device__ __forceinline__ uint64_t mul2(uint64_t a, uint64_t b) {
    uint64_t d; asm("mul.rn.f32x2 %0, %1, %2;" : "=l"(d) : "l"(a), "l"(b)); return d;
}
__device__ __forceinline__ uint64_t add2(uint64_t a, uint64_t b) {
    uint64_t d; asm("add.rn.f32x2 %0, %1, %2;" : "=l"(d) : "l"(a), "l"(b)); return d;
}
__device__ __forceinline__ uint64_t pack2(float lo, float hi) {
    uint64_t d; asm("mov.b64 %0, {%1, %2};" : "=l"(d) : "f"(lo), "f"(hi)); return d;
}
__device__ __forceinline__ uint64_t dup2(float x) {
    uint64_t d; asm("mov.b64 %0, {%1, %1};" : "=l"(d) : "f"(x)); return d;
}

// Weight blob: pre-packed layouts so every fma2 operand is a natural LDC.128.
struct CWts {
    float4 qk4[CH_Y][CH_IN / 2]; // [o][c2]: {Wq[o][2c2],Wk[o][2c2],Wq[o][2c2+1],Wk[o][2c2+1]}
    float4 vT4[CH_IN][4];        // [c][m]:  {Wv[4m][c],Wv[4m+1][c],Wv[4m+2][c],Wv[4m+3][c]}
    float4 wy4[CH_IN][4];        // [ic][m]: Wy row-major (o-pairs natural)
    float2 bqk[CH_Y];            // {bq[o], bk[o]}
    float2 bv2[CH_Y / 2];        // {bv[2o2], bv[2o2+1]}
    float  by[CH_IN];
};
__constant__ CWts CW;
__device__  CWts CW_stage;       // scratch (allowed: __device__ global)

// Prep: pack/transpose weights into the staging blob (1 block, ~µs).
__global__ void prep_kernel(const float* __restrict__ Wq, const float* __restrict__ Wk,
                            const float* __restrict__ Wv, const float* __restrict__ Wy,
                            const float* __restrict__ bq, const float* __restrict__ bk,
                            const float* __restrict__ bv, const float* __restrict__ by)
{
    int t = threadIdx.x;                      // 256 threads
    {   // qk4: 256 float4s, one per thread
        int o = t >> 4, c2 = t & 15;
        CW_stage.qk4[o][c2] = make_float4(
            Wq[o * CH_IN + 2 * c2],     Wk[o * CH_IN + 2 * c2],
            Wq[o * CH_IN + 2 * c2 + 1], Wk[o * CH_IN + 2 * c2 + 1]);
    }
    if (t < CH_IN * 4) {                      // vT4: transposed V weights
        int c = t >> 2, m = t & 3;
        CW_stage.vT4[c][m] = make_float4(
            Wv[(4 * m + 0) * CH_IN + c], Wv[(4 * m + 1) * CH_IN + c],
            Wv[(4 * m + 2) * CH_IN + c], Wv[(4 * m + 3) * CH_IN + c]);
    }
    if (t < CH_IN * 4)                        // wy4: plain copy
        ((float4*)CW_stage.wy4)[t] = ((const float4*)Wy)[t];
    if (t < CH_Y)     CW_stage.bqk[t] = make_float2(bq[t], bk[t]);
    if (t < CH_Y / 2) CW_stage.bv2[t] = make_float2(bv[2 * t], bv[2 * t + 1]);
    if (t < CH_IN)    CW_stage.by[t]  = by[t];
}

// Main: R6 skeleton, weights via constant port instead of smem.
// qk accumulator lane-pair = (q_o, k_o) for one pixel; input = packed (c,p).
__global__ void __launch_bounds__(NT, 4) cross_attn_kernel(
    const float* __restrict__ cin, const float* __restrict__ pin,
    float* __restrict__ out)
{
    __shared__ float    sp[CH_IN * IMG_W];    // 32KB: p row [ch][w]
    __shared__ uint64_t red[4][8];

    const int tid = threadIdx.x;
    const int h = blockIdx.x & (IMG_H - 1);
    const int b = blockIdx.x >> 8;

    const size_t base = (size_t)b * CH_IN * CHS + (size_t)h * IMG_W;
    const float4* cg = (const float4*)(cin + base);
    const float4* pg = (const float4*)(pin + base);
    float4* ocg = (float4*)(out + (size_t)b * 2 * CH_IN * CHS + (size_t)CH_IN * CHS
                                + (size_t)h * IMG_W);
    float4* sp4 = (float4*)sp;

    // ---------------- Phase 1: stage p + concat copy of c ----------------
#pragma unroll
    for (int half = 0; half < 2; half++) {
        float4 cb[8], pb[8];
#pragma unroll
        for (int i = 0; i < 8; i++) {
            int idx = tid + (half * 8 + i) * NT;            // = ch*64 + w4
            int ch = idx >> 6, w4 = idx & 63;
            cb[i] = cg[(size_t)ch * CHS4 + w4];
            pb[i] = pg[(size_t)ch * CHS4 + w4];
        }
#pragma unroll
        for (int i = 0; i < 8; i++) {
            int idx = tid + (half * 8 + i) * NT;
            int ch = idx >> 6, w4 = idx & 63;
            ocg[(size_t)ch * CHS4 + w4] = cb[i];            // concat(c) half
            sp4[idx] = pb[i];
        }
    }
    __syncthreads();

    // ---------------- Phase 2a: fused q,k projection ----------------
    const float2* cp2 = (const float2*)(cin + base);        // + ch*CHS2 + tid
    const float2* sp2 = (const float2*)sp;                  // + ch*128 + tid

    uint64_t qk[2][CH_Y];                   // [px][o] lanes = (q_o, k_o)
#pragma unroll
    for (int o = 0; o < CH_Y; o++) {
        F2U t; t.f = CW.bqk[o];
        qk[0][o] = t.u; qk[1][o] = t.u;
    }

#pragma unroll
    for (int c4 = 0; c4 < CH_IN / 4; c4++) {
        float2 cv[4], pv[4];
#pragma unroll
        for (int j = 0; j < 4; j++) {
            int ch = c4 * 4 + j;
            cv[j] = cp2[(size_t)ch * CHS2 + tid];           // L2-resident re-read
            pv[j] = sp2[ch * (IMG_W / 2) + tid];
        }
        uint64_t in0[4], in1[4];                            // (c,p) packed per px
#pragma unroll
        for (int j = 0; j < 4; j++) {
            in0[j] = pack2(cv[j].x, pv[j].x);
            in1[j] = pack2(cv[j].y, pv[j].y);
        }
#pragma unroll
        for (int o = 0; o < CH_Y; o++) {
            F4U wA, wB;                                      // LDC.128 x2 = 4 ch
            wA.f = CW.qk4[o][c4 * 2 + 0];
            wB.f = CW.qk4[o][c4 * 2 + 1];
            fma2(qk[0][o], wA.u2.x, in0[0]); fma2(qk[0][o], wA.u2.y, in0[1]);
            fma2(qk[0][o], wB.u2.x, in0[2]); fma2(qk[0][o], wB.u2.y, in0[3]);
            fma2(qk[1][o], wA.u2.x, in1[0]); fma2(qk[1][o], wA.u2.y, in1[1]);
            fma2(qk[1][o], wB.u2.x, in1[2]); fma2(qk[1][o], wB.u2.y, in1[3]);
        }
    }

    // exp(q*k): product of the two lanes of each qk pair. No max-subtraction:
    // |q*k| O(1..10), fp32 exp safe; identical after normalization.
    F2U e2[2][8];                            // [px][o2] o-pairs
#pragma unroll
    for (int px = 0; px < 2; px++)
#pragma unroll
        for (int o2 = 0; o2 < 8; o2++) {
            F2U a, bq_; a.u = qk[px][2 * o2]; bq_.u = qk[px][2 * o2 + 1];
            float e0 = __expf(a.f.x * a.f.y);
            float e1 = __expf(bq_.f.x * bq_.f.y);
            e2[px][o2].u = pack2(e0, e1);
        }

    // ---------------- softmax reduction over width (packed) ----------------
    const int lane = tid & 31;
    const int wrp  = tid >> 5;
#pragma unroll
    for (int o2 = 0; o2 < 8; o2++) {
        uint64_t s = add2(e2[0][o2].u, e2[1][o2].u);
#pragma unroll
        for (int d = 16; d > 0; d >>= 1)
            s = add2(s, __shfl_xor_sync(0xffffffffu, (unsigned long long)s, d));
        if (lane == 0) red[wrp][o2] = s;
    }
    __syncthreads();

    uint64_t inv2[8];
#pragma unroll
    for (int o2 = 0; o2 < 8; o2++) {
        F2U t; t.u = add2(add2(red[0][o2], red[1][o2]), add2(red[2][o2], red[3][o2]));
        F2U r; r.f.x = __frcp_rn(t.f.x); r.f.y = __frcp_rn(t.f.y);
        inv2[o2] = r.u;
    }

    // ---------------- Phase 2b: v projection (o-packed, const weights) -----
    uint64_t v[2][8];
#pragma unroll
    for (int o2 = 0; o2 < 8; o2++) {
        F2U t; t.f = CW.bv2[o2];
        v[0][o2] = t.u; v[1][o2] = t.u;
    }

#pragma unroll
    for (int c4 = 0; c4 < CH_IN / 4; c4++) {
        float2 pv[4];
#pragma unroll
        for (int j = 0; j < 4; j++)
            pv[j] = sp2[(c4 * 4 + j) * (IMG_W / 2) + tid];
#pragma unroll
        for (int j = 0; j < 4; j++) {
            const int ch = c4 * 4 + j;
            uint64_t px0 = dup2(pv[j].x), px1 = dup2(pv[j].y);
#pragma unroll
            for (int m = 0; m < 4; m++) {                   // 2 o-pairs per m
                F4U w; w.f = CW.vT4[ch][m];
                fma2(v[0][2*m+0], w.u2.x, px0); fma2(v[0][2*m+1], w.u2.y, px0);
                fma2(v[1][2*m+0], w.u2.x, px1); fma2(v[1][2*m+1], w.u2.y, px1);
            }
        }
    }

    // y = softmax(q*k) * v, packed (overwrite e2)
#pragma unroll
    for (int px = 0; px < 2; px++)
#pragma unroll
        for (int o2 = 0; o2 < 8; o2++)
            e2[px][o2].u = mul2(mul2(e2[px][o2].u, inv2[o2]), v[px][o2]);

    // ---------------- output conv1x1 (const wy, o-pairs + horizontal add) --
    float2* oy2 = (float2*)(out + (size_t)b * 2 * CH_IN * CHS + (size_t)h * IMG_W);
#pragma unroll
    for (int ic = 0; ic < CH_IN; ic++) {
        F2U a0; a0.f = make_float2(CW.by[ic], 0.f);
        uint64_t acc0 = a0.u, acc1 = a0.u;
#pragma unroll
        for (int m = 0; m < 4; m++) {
            F4U w; w.f = CW.wy4[ic][m];                     // o-pairs (2m, 2m+1)
            fma2(acc0, w.u2.x, e2[0][2*m+0].u); fma2(acc0, w.u2.y, e2[0][2*m+1].u);
            fma2(acc1, w.u2.x, e2[1][2*m+0].u); fma2(acc1, w.u2.y, e2[1][2*m+1].u);
        }
        F2U r0, r1; r0.u = acc0; r1.u = acc1;
        oy2[(size_t)ic * CHS2 + tid] = make_float2(r0.f.x + r0.f.y,
                                                   r1.f.x + r1.f.y);
    }
}

extern "C" void kernel_launch(void* const* d_in, const int* in_sizes, int n_in,
                              void* d_out, int out_size)
{
    // 1) pack/transpose weights into __device__ staging blob
    prep_kernel<<<1, 256>>>(
        (const float*)d_in[2], (const float*)d_in[4],   // Wq, Wk
        (const float*)d_in[6], (const float*)d_in[8],   // Wv, Wy
        (const float*)d_in[3], (const float*)d_in[5],   // bq, bk
        (const float*)d_in[7], (const float*)d_in[9]);  // bv, by

    // 2) blob -> __constant__ (D2D memcpy node; graph-capturable)
    void* stage_ptr = nullptr;
    cudaGetSymbolAddress(&stage_ptr, CW_stage);
    cudaMemcpyToSymbolAsync(CW, stage_ptr, sizeof(CWts), 0,
                            cudaMemcpyDeviceToDevice, 0);

    // 3) main kernel
    cross_attn_kernel<<<NB * IMG_H, NT>>>(
        (const float*)d_in[0],  // c
        (const float*)d_in[1],  // p
        (float*)d_out);
}